// round 13
// baseline (speedup 1.0000x reference)
#include <cuda_runtime.h>

// ----------------------------------------------------------------------------
// Tropical (max-plus) ViT, fp32.  C[m,n] = max_k (A[m,k]+B[n,k]) everywhere.
// Round 12: chain collapsed 18 -> 12 graph nodes. Residual/combine folded into
// the NEXT GEMM's A-loader (redundant identical work, benign race), pool
// folded into head, atomic arrays self-resetting (no memset).
// GEMM core = r9 (FADD2), best measured.
// ----------------------------------------------------------------------------

#define NEG_INF (-3.0e38f)
#define BB     8
#define NPATCH 196
#define DD     128
#define DFF    256
#define NPAD   224
#define MTOT   1568
#define NCLS   1000

__device__ float g_h  [MTOT * DD];
__device__ float g_q  [MTOT * DD];
__device__ float g_k  [MTOT * DD];
__device__ float g_vT [BB * DD * NPAD];      // [b][d][j], j-pads stay 0
__device__ float g_s  [BB * NPATCH * NPAD];  // [b][i][j], j-pads = -inf
__device__ float g_p  [4][MTOT * DD];        // pA0,pA1,pB0,pB1 split-K parts
__device__ float g_h1 [MTOT * DFF];
// rowmax atomics: rmE, rmAt0, rmFf0, rmAt1, rmFf1 (self-resetting)
__device__ unsigned g_atoms[5 * MTOT];

enum { M_EMBED, M_QKV, M_SCORES, M_ATT, M_FF1, M_FF2 };
// RMODE: 0 = plain A loads; 1 = A := max(p0,p1), writeback (embed combine);
//        2 = A := max(A, max(p0,p1) - rmApply[row]), writeback (residual)

__device__ __forceinline__ unsigned f2ord(float f) {
    unsigned u = __float_as_uint(f);
    return u ^ ((unsigned)((int)u >> 31) | 0x80000000u);
}
__device__ __forceinline__ float ord2f(unsigned u) {
    unsigned v = (u & 0x80000000u) ? (u ^ 0x80000000u) : ~u;
    return __uint_as_float(v);
}
__device__ __forceinline__ float4 f4max(float4 a, float4 b) {
    a.x = fmaxf(a.x, b.x); a.y = fmaxf(a.y, b.y);
    a.z = fmaxf(a.z, b.z); a.w = fmaxf(a.w, b.w);
    return a;
}
__device__ __forceinline__ float4 f4maxsub(float4 a, float4 b, float rm) {
    a.x = fmaxf(a.x, b.x - rm); a.y = fmaxf(a.y, b.y - rm);
    a.z = fmaxf(a.z, b.z - rm); a.w = fmaxf(a.w, b.w - rm);
    return a;
}

// ---------------------------------------------------------------------------
// Tropical NT GEMM: 32x32 block tile, 128 threads, 2x4 per thread, FADD2.
// ---------------------------------------------------------------------------
template<int MODE, int RMODE>
__global__ __launch_bounds__(128) void tg(
    const float* __restrict__ A, const float* __restrict__ B,
    const float* __restrict__ B2, const float* __restrict__ B3,
    const float* __restrict__ pR0, const float* __restrict__ pR1,
    float* __restrict__ hWB,
    float* __restrict__ C0, float* __restrict__ C1, float* __restrict__ C2,
    const unsigned* __restrict__ rmE, unsigned* __restrict__ rmAtom,
    const unsigned* __restrict__ rmApply,
    const float* __restrict__ aux, unsigned* __restrict__ resetPtr,
    int M, int N, int K, int ldc,
    int aBatch, int bBatch, int cBatch,
    int splitShift, int kPerSplit)
{
    __shared__ __align__(16) float As[32][34];
    __shared__ __align__(16) float Bs[32][36];

    const int t  = threadIdx.x;
    const int tx = t & 7;          // n group (4 cols)
    const int ty = t >> 3;         // m group (2 rows)
    const int lk = tx << 2;
    const int lr = ty;
    const int bm = blockIdx.y << 5;
    const int bn = blockIdx.x << 5;

    // self-reset of a stale atomic array (target unused by THIS kernel)
    if (resetPtr) {
        int lin = (blockIdx.z * gridDim.y + blockIdx.y) * gridDim.x + blockIdx.x;
        int ri = lin * 128 + t;
        if (ri < MTOT) resetPtr[ri] = 0;
    }

    const int z      = blockIdx.z;
    const int half   = z & ((1 << splitShift) - 1);
    const int batch  = z >> splitShift;
    const int kBegin = half * kPerSplit;
    const int kEnd   = min(K, kBegin + kPerSplit);

    const float* Ab = A + (long)batch * aBatch;
    const float* Bb = B + (long)batch * bBatch;

    const float* arow[2];
    const float* p0row[2];
    const float* p1row[2];
    float*       hrow[2];
    float rmApp2[2] = { 0.f, 0.f };
#pragma unroll
    for (int h = 0; h < 2; ++h) {
        int ra = bm + lr + 16 * h; if (ra > M - 1) ra = M - 1;
        if (MODE == M_EMBED) {
            int b = ra / NPATCH, np = ra % NPATCH;
            arow[h] = A + ((long)(b * 224 + (np / 14) * 16)) * 224 + (np % 14) * 16;
        } else {
            arow[h] = Ab + (long)ra * K;
        }
        if (RMODE > 0) {
            p0row[h] = pR0 + (long)ra * DD;
            p1row[h] = pR1 + (long)ra * DD;
            hrow[h]  = hWB + (long)ra * DD;
            if (RMODE == 2) rmApp2[h] = ord2f(rmApply[ra]);
        }
    }
    const float* brow[2];
#pragma unroll
    for (int h = 0; h < 2; ++h) {
        int rb = bn + lr + 16 * h; if (rb > N - 1) rb = N - 1;
        if (MODE == M_QKV) {
            const float* Bp = rb < 128 ? B : (rb < 256 ? B2 : B3);
            brow[h] = Bp + (long)(rb & 127) * K;
        } else {
            brow[h] = Bb + (long)rb * K;
        }
    }

    float acc[2][4];
#pragma unroll
    for (int i = 0; i < 2; ++i)
#pragma unroll
        for (int j = 0; j < 4; ++j) acc[i][j] = NEG_INF;

    for (int kk = kBegin; kk < kEnd; kk += 32) {
#pragma unroll
        for (int h = 0; h < 2; ++h) {
            float4 va;
            if (MODE == M_EMBED) {
                int j = kk + lk; int pr = j >> 4, pc = j & 15;
                va = *(const float4*)(arow[h] + pr * 224 + pc);
            } else if (RMODE == 1) {
                va = f4max(*(const float4*)(p0row[h] + kk + lk),
                           *(const float4*)(p1row[h] + kk + lk));
                *(float4*)(hrow[h] + kk + lk) = va;        // h writeback
            } else if (RMODE == 2) {
                float4 pm = f4max(*(const float4*)(p0row[h] + kk + lk),
                                  *(const float4*)(p1row[h] + kk + lk));
                va = *(const float4*)(arow[h] + kk + lk);
                va = f4maxsub(va, pm, rmApp2[h]);
                *(float4*)(hrow[h] + kk + lk) = va;        // h writeback
            } else {
                va = *(const float4*)(arow[h] + kk + lk);
            }
            As[lk + 0][lr + 16 * h] = va.x;
            As[lk + 1][lr + 16 * h] = va.y;
            As[lk + 2][lr + 16 * h] = va.z;
            As[lk + 3][lr + 16 * h] = va.w;

            float4 vb = *(const float4*)(brow[h] + kk + lk);
            Bs[lk + 0][lr + 16 * h] = vb.x;
            Bs[lk + 1][lr + 16 * h] = vb.y;
            Bs[lk + 2][lr + 16 * h] = vb.z;
            Bs[lk + 3][lr + 16 * h] = vb.w;
        }
        __syncthreads();
#pragma unroll
        for (int k = 0; k < 32; ++k) {
            float2 av = *(const float2*)&As[k][ty * 2];
            ulonglong2 bq = *(const ulonglong2*)&Bs[k][tx * 4];
            unsigned long long a0p, a1p, t0, t1, t2, t3;
            asm("mov.b64 %0, {%1, %1};" : "=l"(a0p) : "f"(av.x));
            asm("mov.b64 %0, {%1, %1};" : "=l"(a1p) : "f"(av.y));
            asm("add.rn.f32x2 %0, %1, %2;" : "=l"(t0) : "l"(a0p), "l"(bq.x));
            asm("add.rn.f32x2 %0, %1, %2;" : "=l"(t1) : "l"(a0p), "l"(bq.y));
            asm("add.rn.f32x2 %0, %1, %2;" : "=l"(t2) : "l"(a1p), "l"(bq.x));
            asm("add.rn.f32x2 %0, %1, %2;" : "=l"(t3) : "l"(a1p), "l"(bq.y));
            float e0, e1;
            asm("mov.b64 {%0, %1}, %2;" : "=f"(e0), "=f"(e1) : "l"(t0));
            acc[0][0] = fmaxf(acc[0][0], e0);
            acc[0][1] = fmaxf(acc[0][1], e1);
            asm("mov.b64 {%0, %1}, %2;" : "=f"(e0), "=f"(e1) : "l"(t1));
            acc[0][2] = fmaxf(acc[0][2], e0);
            acc[0][3] = fmaxf(acc[0][3], e1);
            asm("mov.b64 {%0, %1}, %2;" : "=f"(e0), "=f"(e1) : "l"(t2));
            acc[1][0] = fmaxf(acc[1][0], e0);
            acc[1][1] = fmaxf(acc[1][1], e1);
            asm("mov.b64 {%0, %1}, %2;" : "=f"(e0), "=f"(e1) : "l"(t3));
            acc[1][2] = fmaxf(acc[1][2], e0);
            acc[1][3] = fmaxf(acc[1][3], e1);
        }
        __syncthreads();
    }

    // ---- epilogue ----
    const bool atomicMode = (MODE == M_EMBED || MODE == M_ATT || MODE == M_FF2);
    float rsub[2] = { 0.f, 0.f };
    if (RMODE > 0) {
#pragma unroll
        for (int i = 0; i < 2; ++i) {
            int r0 = min(bm + ty * 2 + i, M - 1);
            float rv = ord2f(rmE[r0]);
            if (RMODE == 2) rv = fmaxf(rv, 0.f);
            rsub[i] = rv;
        }
    }
    const float tauv = (MODE == M_FF1) ? aux[0] : 0.f;
    float* Ch = (half ? C1 : C0) + (long)batch * cBatch;

    float rmax2[2] = { NEG_INF, NEG_INF };
#pragma unroll
    for (int i = 0; i < 2; ++i) {
        int m = bm + ty * 2 + i;
        bool ok = (m < M);
#pragma unroll
        for (int j = 0; j < 4; ++j) {
            int n = bn + tx * 4 + j;
            float v = acc[i][j];
            if (MODE == M_EMBED) v += aux[(m % NPATCH) * DD + n];
            if (RMODE > 0) v -= rsub[i];
            if (MODE == M_FF1) v = fmaxf(v, tauv);
            if (atomicMode) rmax2[i] = fmaxf(rmax2[i], v);
            if (!ok) continue;
            if (MODE == M_QKV) {
                if (n < DD)            C0[(long)m * DD + n] = v;
                else if (n < 2 * DD)   C1[(long)m * DD + (n - DD)] = v;
                else {
                    int b = m / NPATCH, ii = m % NPATCH;
                    C2[((long)b * DD + (n - 2 * DD)) * NPAD + ii] = v;
                }
            } else if (MODE == M_SCORES) {
                Ch[(long)m * ldc + n] = (n < N) ? v : NEG_INF;
            } else {
                Ch[(long)m * ldc + n] = v;
            }
        }
    }

    if (atomicMode) {
#pragma unroll
        for (int i = 0; i < 2; ++i) {
            float rm = rmax2[i];
#pragma unroll
            for (int o = 1; o < 8; o <<= 1)
                rm = fmaxf(rm, __shfl_xor_sync(0xffffffffu, rm, o));
            int m = bm + ty * 2 + i;
            if (tx == 0 && m < M) {
                int row = (MODE == M_ATT) ? batch * NPATCH + m : m;
                atomicMax(&rmAtom[row], f2ord(rm));
            }
        }
    }
}

// head: apply last ff residual on the fly, pool over patches, logits.
// Also resets rmE for the next graph replay.
__global__ void head_k(const float* __restrict__ W, const float* __restrict__ ls,
                       const float* __restrict__ h,
                       const float* __restrict__ p0, const float* __restrict__ p1,
                       const unsigned* __restrict__ rmFf,
                       unsigned* __restrict__ rmReset,
                       float* __restrict__ out)
{
    __shared__ float p[DD];
    int b = blockIdx.y, t = threadIdx.x;
    {
        int lin = blockIdx.y * gridDim.x + blockIdx.x;
        int ri = lin * 128 + t;
        if (ri < MTOT) rmReset[ri] = 0;
    }
    float acc = NEG_INF;
    long base = (long)b * NPATCH * DD + t;
#pragma unroll 2
    for (int n = 0; n < NPATCH; ++n) {
        long idx = base + (long)n * DD;
        float rm = fmaxf(ord2f(rmFf[b * NPATCH + n]), 0.f) -
                   fmaxf(ord2f(rmFf[b * NPATCH + n]), 0.f);   // 0 (keep rm below)
        float rmv = ord2f(rmFf[b * NPATCH + n]);
        float pm = fmaxf(p0[idx], p1[idx]);
        float hv = fmaxf(h[idx], pm - rmv + rm);
        acc = fmaxf(acc, hv);
    }
    p[t] = acc;
    __syncthreads();
    int c = blockIdx.x * 128 + t;
    if (c < NCLS) {
        float a2 = NEG_INF;
        const float* w = W + (long)c * DD;
#pragma unroll 4
        for (int d = 0; d < DD; ++d) a2 = fmaxf(a2, p[d] + w[d]);
        out[(long)b * NCLS + c] = a2 * ls[0];
    }
}

// ---------------------------------------------------------------------------

extern "C" void kernel_launch(void* const* d_in, const int* in_sizes, int n_in,
                              void* d_out, int out_size)
{
    (void)in_sizes; (void)n_in; (void)out_size;
    const float* x       = (const float*)d_in[0];
    const float* embed_W = (const float*)d_in[1];
    const float* pos     = (const float*)d_in[2];
    const float* head_W  = (const float*)d_in[15];
    const float* lscale  = (const float*)d_in[16];
    float* out = (float*)d_out;

    float *h, *q, *k, *vT, *s, *p, *h1;
    unsigned* at;
    cudaGetSymbolAddress((void**)&h,   g_h);
    cudaGetSymbolAddress((void**)&q,   g_q);
    cudaGetSymbolAddress((void**)&k,   g_k);
    cudaGetSymbolAddress((void**)&vT,  g_vT);
    cudaGetSymbolAddress((void**)&s,   g_s);
    cudaGetSymbolAddress((void**)&p,   g_p);
    cudaGetSymbolAddress((void**)&h1,  g_h1);
    cudaGetSymbolAddress((void**)&at,  g_atoms);

    float *pA0 = p,              *pA1 = p + 1 * MTOT * DD;
    float *pB0 = p + 2 * MTOT * DD, *pB1 = p + 3 * MTOT * DD;
    unsigned *rmE   = at;
    unsigned *rmAt0 = at + 1 * MTOT, *rmFf0 = at + 2 * MTOT;
    unsigned *rmAt1 = at + 3 * MTOT, *rmFf1 = at + 4 * MTOT;

    // 1) embed: patchify fused, K=256 split2 -> pB0/pB1 + rmE. Resets rmFf1.
    tg<M_EMBED, 0><<<dim3(4, 49, 2), 128>>>(x, embed_W, 0, 0,
        0, 0, 0, pB0, pB1, 0, 0, rmE, 0, pos, rmFf1,
        MTOT, DD, 256, DD, 0, 0, 0, 1, 128);

    for (int l = 0; l < 2; ++l) {
        const float* qW  = (const float*)d_in[3 + 6 * l];
        const float* kW  = (const float*)d_in[4 + 6 * l];
        const float* vW  = (const float*)d_in[5 + 6 * l];
        const float* f1W = (const float*)d_in[6 + 6 * l];
        const float* f2W = (const float*)d_in[7 + 6 * l];
        const float* tau = (const float*)d_in[8 + 6 * l];
        unsigned* rmAt = l ? rmAt1 : rmAt0;
        unsigned* rmFf = l ? rmFf1 : rmFf0;

        // 2/7) qkv: loader builds/updates h (writeback), subtracts rowmax.
        if (l == 0)
            tg<M_QKV, 1><<<dim3(12, 49, 1), 128>>>(h, qW, kW, vW,
                pB0, pB1, h, q, k, vT, rmE, 0, 0, 0, rmAt0,
                MTOT, 384, DD, 0, 0, 0, 0, 0, DD);
        else
            tg<M_QKV, 2><<<dim3(12, 49, 1), 128>>>(h, qW, kW, vW,
                pB0, pB1, h, q, k, vT, rmE, 0, rmFf0, 0, rmAt1,
                MTOT, 384, DD, 0, 0, 0, 0, 0, DD);

        // 3/8) scores per batch. Layer-0 instance resets rmFf0.
        tg<M_SCORES, 0><<<dim3(7, 7, 8), 128>>>(q, k, 0, 0,
            0, 0, 0, s, 0, 0, 0, 0, 0, 0, (l == 0) ? rmFf0 : 0,
            NPATCH, NPATCH, DD, NPAD,
            NPATCH * DD, NPATCH * DD, NPATCH * NPAD, 0, DD);

        // 4/9) attn out per batch: K=224 split2 -> pA0/pA1 + rmAt.
        tg<M_ATT, 0><<<dim3(4, 7, 16), 128>>>(s, vT, 0, 0,
            0, 0, 0, pA0, pA1, 0, 0, rmAt, 0, 0, 0,
            NPATCH, DD, NPAD, DD,
            NPATCH * NPAD, DD * NPAD, NPATCH * DD, 1, 128);

        // 5/10) ff1: loader applies attn residual to h (writeback), subtracts
        // rowmax, epilogue applies tau -> h1.
        tg<M_FF1, 2><<<dim3(8, 49, 1), 128>>>(h, f1W, 0, 0,
            pA0, pA1, h, h1, 0, 0, rmE, 0, rmAt, tau, 0,
            MTOT, DFF, DD, DFF, 0, 0, 0, 0, DD);

        // 6/11) ff2: K=256 split2 -> pB0/pB1 + rmFf.
        tg<M_FF2, 0><<<dim3(4, 49, 2), 128>>>(h1, f2W, 0, 0,
            0, 0, 0, pB0, pB1, 0, 0, rmFf, 0, 0, 0,
            MTOT, DD, DFF, DD, 0, 0, 0, 1, 128);
    }

    // 12) head: final residual + pool + logits. Resets rmE.
    head_k<<<dim3(8, BB), 128>>>(head_W, lscale, h, pB0, pB1, rmFf1, rmE, out);
}